// round 13
// baseline (speedup 1.0000x reference)
#include <cuda_runtime.h>

#define THREADS 512
#define BM 32
static constexpr int TSTEPS = 200;
using ull = unsigned long long;

// Pre-duplicated weights: Wd[k][2c] = Wd[k][2c+1] = W[k][c]
__device__ float W1d[64 * 512];
__device__ float W2d[256 * 512];
__device__ float W3d[256 * 128];

__global__ void dup_weights_kernel(const float* __restrict__ W1,
                                   const float* __restrict__ W2,
                                   const float* __restrict__ W3)
{
    int i = blockIdx.x * blockDim.x + threadIdx.x;
    if (i < 64 * 256) {
        float v = W1[i]; int k = i >> 8, c = i & 255;
        W1d[k * 512 + 2 * c] = v; W1d[k * 512 + 2 * c + 1] = v;
    }
    if (i < 256 * 256) {
        float v = W2[i]; int k = i >> 8, c = i & 255;
        W2d[k * 512 + 2 * c] = v; W2d[k * 512 + 2 * c + 1] = v;
    }
    if (i < 256 * 64) {
        float v = W3[i]; int k = i >> 6, c = i & 63;
        W3d[k * 128 + 2 * c] = v; W3d[k * 128 + 2 * c + 1] = v;
    }
}

__device__ __forceinline__ ull dup2(float v) {
    ull r; asm("mov.b64 %0, {%1, %1};" : "=l"(r) : "r"(__float_as_uint(v)));
    return r;
}
__device__ __forceinline__ ull pack2(float x, float y) {
    ull r; asm("mov.b64 %0, {%1, %2};" : "=l"(r)
               : "r"(__float_as_uint(x)), "r"(__float_as_uint(y)));
    return r;
}
__device__ __forceinline__ float2 unpk(ull p) {
    unsigned lo, hi;
    asm("mov.b64 {%0, %1}, %2;" : "=r"(lo), "=r"(hi) : "l"(p));
    return make_float2(__uint_as_float(lo), __uint_as_float(hi));
}
__device__ __forceinline__ void fma2(ull &d, ull a, ull b) {
    asm("fma.rn.f32x2 %0, %1, %2, %0;" : "+l"(d) : "l"(a), "l"(b));
}

// smem layout (floats): y_cm[64][32], h1_cm[256][32], h2_cm[256][32], b1, b2, b3
static constexpr int OFF_Y  = 0;
static constexpr int OFF_H1 = OFF_Y  + 64 * 32;
static constexpr int OFF_H2 = OFF_H1 + 256 * 32;
static constexpr int OFF_B1 = OFF_H2 + 256 * 32;
static constexpr int OFF_B2 = OFF_B1 + 256;
static constexpr int OFF_B3 = OFF_B2 + 256;
static constexpr int SMEM_FLOATS = OFF_B3 + 64;
static constexpr int SMEM_BYTES  = SMEM_FLOATS * 4;   // 76,032 B

__global__ void __launch_bounds__(THREADS, 1)
neural_ode_kernel(const float* __restrict__ y0,
                  const float* __restrict__ tarr,
                  const float* __restrict__ b1g,
                  const float* __restrict__ b2g,
                  const float* __restrict__ b3g,
                  float* __restrict__ out)
{
    extern __shared__ float sm[];
    float* smY  = sm + OFF_Y;     // column-major [dim][row], swizzled rows
    float* smH1 = sm + OFF_H1;
    float* smH2 = sm + OFF_H2;
    float* sb1  = sm + OFF_B1;
    float* sb2  = sm + OFF_B2;
    float* sb3  = sm + OFF_B3;

    const int tid  = threadIdx.x;
    const int row0 = blockIdx.x * BM;

    if (tid < 256) { sb1[tid] = b1g[tid]; sb2[tid] = b2g[tid]; }
    if (tid < 64)  sb3[tid] = b3g[tid];

    // y0 -> column-major swizzled smem; emit t=0 output slice
    for (int i = tid; i < BM * 64; i += THREADS) {
        int r = i >> 6, c = i & 63;
        float v = y0[(size_t)(row0 + r) * 64 + c];
        smY[c * 32 + (r ^ (c & 28))] = v;
        out[((size_t)(row0 + r) * TSTEPS) * 64 + c] = v;
    }
    const float dt = tarr[1] - tarr[0];
    __syncthreads();

    const int wid  = tid >> 5;
    const int lane = tid & 31;
    // GEMM1/2: thread = 4 rows (rbA..rbA+3) x 4 cols (colA..colA+3) of [32][256]
    const int colA = (wid & 7) * 32 + (lane & 7) * 4;
    const int rbA  = (wid >> 3) * 16 + (lane >> 3) * 4;
    // GEMM3: thread = 2 rows (rpC, rpC+1) x 2 cols (colC, colC+1) of [32][64]
    const int colC = (wid & 3) * 16 + (lane & 7) * 2;
    const int rpC  = (wid >> 2) * 8 + (lane >> 3) * 2;

    // biases pre-duplicated into registers (constant across steps)
    ull bd1[4], bd2[4], bd3[2];
    #pragma unroll
    for (int c = 0; c < 4; ++c) {
        bd1[c] = dup2(sb1[colA + c]);
        bd2[c] = dup2(sb2[colA + c]);
    }
    bd3[0] = dup2(sb3[colC]);
    bd3[1] = dup2(sb3[colC + 1]);

    for (int step = 1; step < TSTEPS; ++step) {
        // ======== GEMM1: h1 = relu(y @ W1 + b1), K=64 ========
        {
            ull acc[2][4];
            #pragma unroll
            for (int c = 0; c < 4; ++c) { acc[0][c] = bd1[c]; acc[1][c] = bd1[c]; }
            #pragma unroll 8
            for (int k = 0; k < 64; ++k) {
                const float* wp = &W1d[k * 512 + 2 * colA];
                ulonglong2 w0 = *(const ulonglong2*)(wp);       // dup cols c0,c1
                ulonglong2 w1 = *(const ulonglong2*)(wp + 4);   // dup cols c2,c3
                ulonglong2 a  = *(const ulonglong2*)&smY[k * 32 + (rbA ^ (k & 28))];
                fma2(acc[0][0], a.x, w0.x); fma2(acc[0][1], a.x, w0.y);
                fma2(acc[0][2], a.x, w1.x); fma2(acc[0][3], a.x, w1.y);
                fma2(acc[1][0], a.y, w0.x); fma2(acc[1][1], a.y, w0.y);
                fma2(acc[1][2], a.y, w1.x); fma2(acc[1][3], a.y, w1.y);
            }
            #pragma unroll
            for (int c = 0; c < 4; ++c) {
                int cc = colA + c, sw = cc & 28;
                #pragma unroll
                for (int p = 0; p < 2; ++p) {
                    float2 v = unpk(acc[p][c]);
                    *(ull*)&smH1[cc * 32 + ((rbA + 2 * p) ^ sw)] =
                        pack2(fmaxf(v.x, 0.f), fmaxf(v.y, 0.f));
                }
            }
        }
        __syncthreads();

        // ======== GEMM2: h2 = relu(h1 @ W2 + b2), K=256 ========
        {
            ull acc[2][4];
            #pragma unroll
            for (int c = 0; c < 4; ++c) { acc[0][c] = bd2[c]; acc[1][c] = bd2[c]; }
            #pragma unroll 8
            for (int k = 0; k < 256; ++k) {
                const float* wp = &W2d[k * 512 + 2 * colA];
                ulonglong2 w0 = *(const ulonglong2*)(wp);
                ulonglong2 w1 = *(const ulonglong2*)(wp + 4);
                ulonglong2 a  = *(const ulonglong2*)&smH1[k * 32 + (rbA ^ (k & 28))];
                fma2(acc[0][0], a.x, w0.x); fma2(acc[0][1], a.x, w0.y);
                fma2(acc[0][2], a.x, w1.x); fma2(acc[0][3], a.x, w1.y);
                fma2(acc[1][0], a.y, w0.x); fma2(acc[1][1], a.y, w0.y);
                fma2(acc[1][2], a.y, w1.x); fma2(acc[1][3], a.y, w1.y);
            }
            #pragma unroll
            for (int c = 0; c < 4; ++c) {
                int cc = colA + c, sw = cc & 28;
                #pragma unroll
                for (int p = 0; p < 2; ++p) {
                    float2 v = unpk(acc[p][c]);
                    *(ull*)&smH2[cc * 32 + ((rbA + 2 * p) ^ sw)] =
                        pack2(fmaxf(v.x, 0.f), fmaxf(v.y, 0.f));
                }
            }
        }
        __syncthreads();

        // ======== GEMM3: y += dt*(h2 @ W3 + b3), K=256 ========
        {
            ull acc3[2] = { bd3[0], bd3[1] };
            #pragma unroll 8
            for (int k = 0; k < 256; ++k) {
                ulonglong2 w = *(const ulonglong2*)&W3d[k * 128 + 2 * colC];
                ull a = *(const ull*)&smH2[k * 32 + (rpC ^ (k & 28))];
                fma2(acc3[0], a, w.x);
                fma2(acc3[1], a, w.y);
            }
            float2 d0 = unpk(acc3[0]);   // col colC,   rows rpC, rpC+1
            float2 d1 = unpk(acc3[1]);   // col colC+1, rows rpC, rpC+1
            int c0 = colC, c1 = colC + 1;
            ull* yp0 = (ull*)&smY[c0 * 32 + (rpC ^ (c0 & 28))];
            ull* yp1 = (ull*)&smY[c1 * 32 + (rpC ^ (c1 & 28))];
            float2 o0 = unpk(*yp0);
            float2 o1 = unpk(*yp1);
            float n00 = o0.x + dt * d0.x;   // row rpC,   col c0
            float n01 = o0.y + dt * d0.y;   // row rpC+1, col c0
            float n10 = o1.x + dt * d1.x;   // row rpC,   col c1
            float n11 = o1.y + dt * d1.y;   // row rpC+1, col c1
            *yp0 = pack2(n00, n01);
            *yp1 = pack2(n10, n11);
            size_t ob = ((size_t)(row0 + rpC) * TSTEPS + step) * 64 + c0;
            *(float2*)(out + ob)                    = make_float2(n00, n10);
            *(float2*)(out + ob + (size_t)TSTEPS*64) = make_float2(n01, n11);
        }
        __syncthreads();
    }
}

extern "C" void kernel_launch(void* const* d_in, const int* in_sizes, int n_in,
                              void* d_out, int out_size)
{
    const float* y0 = (const float*)d_in[0];
    const float* t  = (const float*)d_in[1];
    const float* W1 = (const float*)d_in[2];
    const float* b1 = (const float*)d_in[3];
    const float* W2 = (const float*)d_in[4];
    const float* b2 = (const float*)d_in[5];
    const float* W3 = (const float*)d_in[6];
    const float* b3 = (const float*)d_in[7];
    float* out = (float*)d_out;

    dup_weights_kernel<<<256, 256>>>(W1, W2, W3);

    cudaFuncSetAttribute(neural_ode_kernel,
                         cudaFuncAttributeMaxDynamicSharedMemorySize,
                         SMEM_BYTES);

    int B = in_sizes[0] / 64;          // 4096
    int grid = B / BM;                 // 128
    neural_ode_kernel<<<grid, THREADS, SMEM_BYTES>>>(
        y0, t, b1, b2, b3, out);
}

// round 14
// speedup vs baseline: 1.0020x; 1.0020x over previous
#include <cuda_runtime.h>

#define THREADS 512
#define BM 32
static constexpr int TSTEPS = 200;
using ull = unsigned long long;

// Pre-duplicated weights: Wd[k][2c] = Wd[k][2c+1] = W[k][c]
__device__ float W1d[64 * 512];
__device__ float W2d[256 * 512];
__device__ float W3d[256 * 128];

__global__ void dup_weights_kernel(const float* __restrict__ W1,
                                   const float* __restrict__ W2,
                                   const float* __restrict__ W3)
{
    int i = blockIdx.x * blockDim.x + threadIdx.x;
    if (i < 64 * 256) {
        float v = W1[i]; int k = i >> 8, c = i & 255;
        W1d[k * 512 + 2 * c] = v; W1d[k * 512 + 2 * c + 1] = v;
    }
    if (i < 256 * 256) {
        float v = W2[i]; int k = i >> 8, c = i & 255;
        W2d[k * 512 + 2 * c] = v; W2d[k * 512 + 2 * c + 1] = v;
    }
    if (i < 256 * 64) {
        float v = W3[i]; int k = i >> 6, c = i & 63;
        W3d[k * 128 + 2 * c] = v; W3d[k * 128 + 2 * c + 1] = v;
    }
}

__device__ __forceinline__ ull dup2(float v) {
    ull r; asm("mov.b64 %0, {%1, %1};" : "=l"(r) : "r"(__float_as_uint(v)));
    return r;
}
__device__ __forceinline__ ull pack2(float x, float y) {
    ull r; asm("mov.b64 %0, {%1, %2};" : "=l"(r)
               : "r"(__float_as_uint(x)), "r"(__float_as_uint(y)));
    return r;
}
__device__ __forceinline__ float2 unpk(ull p) {
    unsigned lo, hi;
    asm("mov.b64 {%0, %1}, %2;" : "=r"(lo), "=r"(hi) : "l"(p));
    return make_float2(__uint_as_float(lo), __uint_as_float(hi));
}
__device__ __forceinline__ void fma2(ull &d, ull a, ull b) {
    asm("fma.rn.f32x2 %0, %1, %2, %0;" : "+l"(d) : "l"(a), "l"(b));
}

// smem layout (floats): y_cm[64][32], h1_cm[256][32], h2_cm[256][32], b1, b2, b3
static constexpr int OFF_Y  = 0;
static constexpr int OFF_H1 = OFF_Y  + 64 * 32;
static constexpr int OFF_H2 = OFF_H1 + 256 * 32;
static constexpr int OFF_B1 = OFF_H2 + 256 * 32;
static constexpr int OFF_B2 = OFF_B1 + 256;
static constexpr int OFF_B3 = OFF_B2 + 256;
static constexpr int SMEM_FLOATS = OFF_B3 + 64;
static constexpr int SMEM_BYTES  = SMEM_FLOATS * 4;   // 76,032 B

__global__ void __launch_bounds__(THREADS, 1)
neural_ode_kernel(const float* __restrict__ y0,
                  const float* __restrict__ tarr,
                  const float* __restrict__ b1g,
                  const float* __restrict__ b2g,
                  const float* __restrict__ b3g,
                  float* __restrict__ out)
{
    extern __shared__ float sm[];
    float* smY  = sm + OFF_Y;     // column-major [dim][row], swizzled rows
    float* smH1 = sm + OFF_H1;
    float* smH2 = sm + OFF_H2;
    float* sb1  = sm + OFF_B1;
    float* sb2  = sm + OFF_B2;
    float* sb3  = sm + OFF_B3;

    const int tid  = threadIdx.x;
    const int row0 = blockIdx.x * BM;

    if (tid < 256) { sb1[tid] = b1g[tid]; sb2[tid] = b2g[tid]; }
    if (tid < 64)  sb3[tid] = b3g[tid];

    // y0 -> column-major swizzled smem; emit t=0 output slice
    for (int i = tid; i < BM * 64; i += THREADS) {
        int r = i >> 6, c = i & 63;
        float v = y0[(size_t)(row0 + r) * 64 + c];
        smY[c * 32 + (r ^ (c & 28))] = v;
        out[((size_t)(row0 + r) * TSTEPS) * 64 + c] = v;
    }
    const float dt = tarr[1] - tarr[0];
    __syncthreads();

    const int wid  = tid >> 5;
    const int lane = tid & 31;
    // GEMM1/2: thread = 4 rows (rbA..rbA+3) x 4 cols (colA..colA+3) of [32][256]
    const int colA = (wid & 7) * 32 + (lane & 7) * 4;
    const int rbA  = (wid >> 3) * 16 + (lane >> 3) * 4;
    // GEMM3: thread = 2 rows (rpC, rpC+1) x 2 cols (colC, colC+1) of [32][64]
    const int colC = (wid & 3) * 16 + (lane & 7) * 2;
    const int rpC  = (wid >> 2) * 8 + (lane >> 3) * 2;

    // biases pre-duplicated into registers (constant across steps)
    ull bd1[4], bd2[4], bd3[2];
    #pragma unroll
    for (int c = 0; c < 4; ++c) {
        bd1[c] = dup2(sb1[colA + c]);
        bd2[c] = dup2(sb2[colA + c]);
    }
    bd3[0] = dup2(sb3[colC]);
    bd3[1] = dup2(sb3[colC + 1]);

    for (int step = 1; step < TSTEPS; ++step) {
        // ======== GEMM1: h1 = relu(y @ W1 + b1), K=64 ========
        {
            ull acc[2][4];
            #pragma unroll
            for (int c = 0; c < 4; ++c) { acc[0][c] = bd1[c]; acc[1][c] = bd1[c]; }
            #pragma unroll 8
            for (int k = 0; k < 64; ++k) {
                const float* wp = &W1d[k * 512 + 2 * colA];
                ulonglong2 w0 = *(const ulonglong2*)(wp);       // dup cols c0,c1
                ulonglong2 w1 = *(const ulonglong2*)(wp + 4);   // dup cols c2,c3
                ulonglong2 a  = *(const ulonglong2*)&smY[k * 32 + (rbA ^ (k & 28))];
                fma2(acc[0][0], a.x, w0.x); fma2(acc[0][1], a.x, w0.y);
                fma2(acc[0][2], a.x, w1.x); fma2(acc[0][3], a.x, w1.y);
                fma2(acc[1][0], a.y, w0.x); fma2(acc[1][1], a.y, w0.y);
                fma2(acc[1][2], a.y, w1.x); fma2(acc[1][3], a.y, w1.y);
            }
            #pragma unroll
            for (int c = 0; c < 4; ++c) {
                int cc = colA + c, sw = cc & 28;
                #pragma unroll
                for (int p = 0; p < 2; ++p) {
                    float2 v = unpk(acc[p][c]);
                    *(ull*)&smH1[cc * 32 + ((rbA + 2 * p) ^ sw)] =
                        pack2(fmaxf(v.x, 0.f), fmaxf(v.y, 0.f));
                }
            }
        }
        __syncthreads();

        // ======== GEMM2: h2 = relu(h1 @ W2 + b2), K=256 ========
        {
            ull acc[2][4];
            #pragma unroll
            for (int c = 0; c < 4; ++c) { acc[0][c] = bd2[c]; acc[1][c] = bd2[c]; }
            #pragma unroll 8
            for (int k = 0; k < 256; ++k) {
                const float* wp = &W2d[k * 512 + 2 * colA];
                ulonglong2 w0 = *(const ulonglong2*)(wp);
                ulonglong2 w1 = *(const ulonglong2*)(wp + 4);
                ulonglong2 a  = *(const ulonglong2*)&smH1[k * 32 + (rbA ^ (k & 28))];
                fma2(acc[0][0], a.x, w0.x); fma2(acc[0][1], a.x, w0.y);
                fma2(acc[0][2], a.x, w1.x); fma2(acc[0][3], a.x, w1.y);
                fma2(acc[1][0], a.y, w0.x); fma2(acc[1][1], a.y, w0.y);
                fma2(acc[1][2], a.y, w1.x); fma2(acc[1][3], a.y, w1.y);
            }
            #pragma unroll
            for (int c = 0; c < 4; ++c) {
                int cc = colA + c, sw = cc & 28;
                #pragma unroll
                for (int p = 0; p < 2; ++p) {
                    float2 v = unpk(acc[p][c]);
                    *(ull*)&smH2[cc * 32 + ((rbA + 2 * p) ^ sw)] =
                        pack2(fmaxf(v.x, 0.f), fmaxf(v.y, 0.f));
                }
            }
        }
        __syncthreads();

        // ======== GEMM3: y += dt*(h2 @ W3 + b3), K=256 ========
        {
            ull acc3[2] = { bd3[0], bd3[1] };
            #pragma unroll 8
            for (int k = 0; k < 256; ++k) {
                ulonglong2 w = *(const ulonglong2*)&W3d[k * 128 + 2 * colC];
                ull a = *(const ull*)&smH2[k * 32 + (rpC ^ (k & 28))];
                fma2(acc3[0], a, w.x);
                fma2(acc3[1], a, w.y);
            }
            float2 d0 = unpk(acc3[0]);   // col colC,   rows rpC, rpC+1
            float2 d1 = unpk(acc3[1]);   // col colC+1, rows rpC, rpC+1
            int c0 = colC, c1 = colC + 1;
            ull* yp0 = (ull*)&smY[c0 * 32 + (rpC ^ (c0 & 28))];
            ull* yp1 = (ull*)&smY[c1 * 32 + (rpC ^ (c1 & 28))];
            float2 o0 = unpk(*yp0);
            float2 o1 = unpk(*yp1);
            float n00 = o0.x + dt * d0.x;   // row rpC,   col c0
            float n01 = o0.y + dt * d0.y;   // row rpC+1, col c0
            float n10 = o1.x + dt * d1.x;   // row rpC,   col c1
            float n11 = o1.y + dt * d1.y;   // row rpC+1, col c1
            *yp0 = pack2(n00, n01);
            *yp1 = pack2(n10, n11);
            size_t ob = ((size_t)(row0 + rpC) * TSTEPS + step) * 64 + c0;
            *(float2*)(out + ob)                    = make_float2(n00, n10);
            *(float2*)(out + ob + (size_t)TSTEPS*64) = make_float2(n01, n11);
        }
        __syncthreads();
    }
}

extern "C" void kernel_launch(void* const* d_in, const int* in_sizes, int n_in,
                              void* d_out, int out_size)
{
    const float* y0 = (const float*)d_in[0];
    const float* t  = (const float*)d_in[1];
    const float* W1 = (const float*)d_in[2];
    const float* b1 = (const float*)d_in[3];
    const float* W2 = (const float*)d_in[4];
    const float* b2 = (const float*)d_in[5];
    const float* W3 = (const float*)d_in[6];
    const float* b3 = (const float*)d_in[7];
    float* out = (float*)d_out;

    dup_weights_kernel<<<256, 256>>>(W1, W2, W3);

    cudaFuncSetAttribute(neural_ode_kernel,
                         cudaFuncAttributeMaxDynamicSharedMemorySize,
                         SMEM_BYTES);

    int B = in_sizes[0] / 64;          // 4096
    int grid = B / BM;                 // 128
    neural_ode_kernel<<<grid, THREADS, SMEM_BYTES>>>(
        y0, t, b1, b2, b3, out);
}